// round 1
// baseline (speedup 1.0000x reference)
#include <cuda_runtime.h>
#include <math.h>

#define NN 1024
#define DIM 64
#define NH 64
#define QW 192            // qkv row width (3*DIM)
#define NC 13             // Taylor terms (degree 12)
#define SCALE 0.125f
#define KMAX 20

// -------- device scratch (no allocations allowed) --------
__device__ float g_xm[NN*DIM];        // masked x
__device__ float g_qkv[NN*QW];        // local qkv
__device__ float g_gqkv[NN*QW];       // global qkv
__device__ float g_cD[NH][NC];        // per-head denominator Taylor coeffs
__device__ float g_topk[NH][KMAX];    // top-20 k values (desc, tie low idx)
__device__ float g_topv[NH][KMAX];
__device__ float g_botk[NH][KMAX];    // bottom-20 k values (asc, tie low idx)
__device__ float g_botv[NH][KMAX];
__device__ float g_entpart[NH];
__device__ float g_gx[NN*DIM];        // global attention output
__device__ float g_lx[NN*DIM];        // local attention output
__device__ int   g_km;
__device__ int   g_early;

__constant__ float c_invf[14] = {
    1.0f, 1.0f, 0.5f, 1.66666672e-01f, 4.16666679e-02f, 8.33333377e-03f,
    1.38888892e-03f, 1.98412701e-04f, 2.48015876e-05f, 2.75573188e-06f,
    2.75573192e-07f, 2.50521084e-08f, 2.08767563e-09f, 1.60590438e-10f };

__device__ __forceinline__ unsigned int ford(float f) {
    unsigned int u = __float_as_uint(f);
    return (u & 0x80000000u) ? ~u : (u | 0x80000000u);
}

__device__ __forceinline__ float horner13(const float* c, float a) {
    float r = c[12];
#pragma unroll
    for (int j = 11; j >= 0; --j) r = fmaf(r, a, c[j]);
    return r;
}

// ---------------- kernel 0: importance / early flag ----------------
__global__ void k0_importance(const float* __restrict__ x,
                              const float* __restrict__ hg_w,
                              const float* __restrict__ hg_b) {
    __shared__ float s[DIM];
    int c = threadIdx.x;  // 64 threads
    float acc = 0.f;
    for (int n = 0; n < NN; ++n) acc += x[n*DIM + c];
    s[c] = (acc * (1.f/(float)NN)) * hg_w[c];
    __syncthreads();
    if (c == 0) {
        float l = hg_b[0];
        for (int j = 0; j < DIM; ++j) l += s[j];
        float imp = 1.f / (1.f + expf(-l));
        g_early = (imp < 0.1f) ? 1 : 0;
    }
}

// ---------------- kernel 1: gate mask + qkv / gqkv GEMMs (per row) ----------------
__global__ void k1_gate_qkv(const float* __restrict__ x,
                            const float* __restrict__ cg_w, const float* __restrict__ cg_b,
                            const float* __restrict__ qkv_w, const float* __restrict__ qkv_b,
                            const float* __restrict__ gqkv_w, const float* __restrict__ gqkv_b) {
    int n = blockIdx.x;
    int t = threadIdx.x;  // 192 threads
    __shared__ float xr[DIM], xm[DIM];
    if (t < DIM) xr[t] = x[n*DIM + t];
    __syncthreads();
    if (t < DIM) {
        float l = cg_b[t];
#pragma unroll 8
        for (int j = 0; j < DIM; ++j) l = fmaf(xr[j], cg_w[j*DIM + t], l);
        float g = 1.f / (1.f + expf(-l));
        float v = (g > 0.1f) ? xr[t] : 0.f;
        xm[t] = v;
        g_xm[n*DIM + t] = v;
    }
    __syncthreads();
    float a = qkv_b[t], b = gqkv_b[t];
#pragma unroll 8
    for (int j = 0; j < DIM; ++j) {
        float xv = xm[j];
        a = fmaf(xv, qkv_w[j*QW + t], a);
        b = fmaf(xv, gqkv_w[j*QW + t], b);
    }
    g_qkv[n*QW + t] = a;
    g_gqkv[n*QW + t] = b;
}

// ---------------- kernel 3: per-head moments, top/bottom-20, entropy, global attn ----------------
__global__ void k3_head() {
    int h   = blockIdx.x;
    int tid = threadIdx.x;   // 256
    int lane = tid & 31, wid = tid >> 5;

    __shared__ float kk[NN], vv[NN], gk[NN], gv[NN];
    __shared__ unsigned long long keys[NN];
    __shared__ float redbuf[40][8];
    __shared__ float Rall[40];
    __shared__ float cD[NC], cS1[NC], cDg[NC], cSvg[NC];
    __shared__ unsigned long long wmax[8];

    for (int m = tid; m < NN; m += 256) {
        kk[m] = g_qkv[m*QW + 64 + h];
        vv[m] = g_qkv[m*QW + 128 + h];
        gk[m] = g_gqkv[m*QW + 64 + h];
        gv[m] = g_gqkv[m*QW + 128 + h];
    }
    __syncthreads();

    // ---- moments ----
    float M[NC+1];   // k^0..k^13
    float Mg[NC];    // gk^0..gk^12
    float Wg[NC];    // gv*gk^0..gv*gk^12
#pragma unroll
    for (int j = 0; j <= NC; ++j) M[j] = 0.f;
#pragma unroll
    for (int j = 0; j < NC; ++j) { Mg[j] = 0.f; Wg[j] = 0.f; }

    for (int m = tid; m < NN; m += 256) {
        float kv = kk[m];
        float p = 1.f;
#pragma unroll
        for (int j = 0; j <= NC; ++j) { M[j] += p; p *= kv; }
        float gkv = gk[m], gvv = gv[m];
        float pg = 1.f;
#pragma unroll
        for (int j = 0; j < NC; ++j) { Mg[j] += pg; Wg[j] += gvv * pg; pg *= gkv; }
    }
#pragma unroll
    for (int j = 0; j <= NC; ++j) {
        float v = M[j];
        for (int o = 16; o; o >>= 1) v += __shfl_down_sync(0xffffffffu, v, o);
        if (lane == 0) redbuf[j][wid] = v;
    }
#pragma unroll
    for (int j = 0; j < NC; ++j) {
        float v = Mg[j];
        for (int o = 16; o; o >>= 1) v += __shfl_down_sync(0xffffffffu, v, o);
        if (lane == 0) redbuf[14 + j][wid] = v;
        float w = Wg[j];
        for (int o = 16; o; o >>= 1) w += __shfl_down_sync(0xffffffffu, w, o);
        if (lane == 0) redbuf[27 + j][wid] = w;
    }
    __syncthreads();
    if (tid < 40) {
        float s = 0.f;
#pragma unroll
        for (int w = 0; w < 8; ++w) s += redbuf[tid][w];
        Rall[tid] = s;
    }
    __syncthreads();
    if (tid < NC) {
        float f = c_invf[tid];
        cD[tid]   = Rall[tid]      * f;
        cS1[tid]  = Rall[tid + 1]  * f;
        cDg[tid]  = Rall[14 + tid] * f;
        cSvg[tid] = Rall[27 + tid] * f;
        g_cD[h][tid] = cD[tid];
    }
    __syncthreads();

    // ---- top-20 (descending k, tie -> lower index) ----
    for (int m = tid; m < NN; m += 256) {
        unsigned int ov = ford(kk[m]);
        keys[m] = ((unsigned long long)ov << 32) | (unsigned int)(1023 - m);
    }
    __syncthreads();
    for (int i = 0; i < KMAX; ++i) {
        unsigned long long loc = 0ull;
        for (int m = tid; m < NN; m += 256) { unsigned long long kq = keys[m]; if (kq > loc) loc = kq; }
        for (int o = 16; o; o >>= 1) {
            unsigned long long other = __shfl_down_sync(0xffffffffu, loc, o);
            if (other > loc) loc = other;
        }
        if (lane == 0) wmax[wid] = loc;
        __syncthreads();
        if (tid == 0) {
            unsigned long long mx = wmax[0];
#pragma unroll
            for (int w = 1; w < 8; ++w) if (wmax[w] > mx) mx = wmax[w];
            int m = 1023 - (int)(unsigned int)(mx & 0xFFFFFFFFull);
            keys[m] = 0ull;
            g_topk[h][i] = kk[m];
            g_topv[h][i] = vv[m];
        }
        __syncthreads();
    }

    // ---- bottom-20 (ascending k, tie -> lower index) ----
    for (int m = tid; m < NN; m += 256) {
        unsigned int ov = ~ford(kk[m]);
        keys[m] = ((unsigned long long)ov << 32) | (unsigned int)(1023 - m);
    }
    __syncthreads();
    for (int i = 0; i < KMAX; ++i) {
        unsigned long long loc = 0ull;
        for (int m = tid; m < NN; m += 256) { unsigned long long kq = keys[m]; if (kq > loc) loc = kq; }
        for (int o = 16; o; o >>= 1) {
            unsigned long long other = __shfl_down_sync(0xffffffffu, loc, o);
            if (other > loc) loc = other;
        }
        if (lane == 0) wmax[wid] = loc;
        __syncthreads();
        if (tid == 0) {
            unsigned long long mx = wmax[0];
#pragma unroll
            for (int w = 1; w < 8; ++w) if (wmax[w] > mx) mx = wmax[w];
            int m = 1023 - (int)(unsigned int)(mx & 0xFFFFFFFFull);
            keys[m] = 0ull;
            g_botk[h][i] = kk[m];
            g_botv[h][i] = vv[m];
        }
        __syncthreads();
    }

    // ---- entropy + global attention output ----
    float entacc = 0.f;
    for (int n = tid; n < NN; n += 256) {
        float a = g_qkv[n*QW + h] * SCALE;
        float D  = horner13(cD, a);
        float S1 = horner13(cS1, a);
        entacc += logf(D) - a * S1 / D;

        float ag = g_gqkv[n*QW + h] * SCALE;
        float Dg = horner13(cDg, ag);
        float Sv = horner13(cSvg, ag);
        g_gx[n*DIM + h] = Sv / Dg;
    }
    for (int o = 16; o; o >>= 1) entacc += __shfl_down_sync(0xffffffffu, entacc, o);
    if (lane == 0) redbuf[0][wid] = entacc;
    __syncthreads();
    if (tid == 0) {
        float s = 0.f;
#pragma unroll
        for (int w = 0; w < 8; ++w) s += redbuf[0][w];
        g_entpart[h] = s;
    }
}

// ---------------- kernel 3b: km from mean entropy ----------------
__global__ void k3b_km() {
    if (threadIdx.x == 0) {
        float s = 0.f;
        for (int hh = 0; hh < NH; ++hh) s += g_entpart[hh];
        float em = s * (1.f / (float)(NH * NN));
        int km = 5 + (int)rintf(15.f * em);
        if (km < 5) km = 5;
        if (km > 20) km = 20;
        g_km = km;
    }
}

// ---------------- kernel 4: local (top-km) attention output ----------------
__global__ void k4_local() {
    int h = blockIdx.x, tid = threadIdx.x;  // 256
    __shared__ float tk[KMAX], tv[KMAX], bk[KMAX], bv[KMAX], cD[NC];
    __shared__ int km_s;
    if (tid < KMAX) {
        tk[tid] = g_topk[h][tid]; tv[tid] = g_topv[h][tid];
        bk[tid] = g_botk[h][tid]; bv[tid] = g_botv[h][tid];
    }
    if (tid < NC) cD[tid] = g_cD[h][tid];
    if (tid == 0) km_s = g_km;
    __syncthreads();
    int km = km_s;
    for (int n = tid; n < NN; n += 256) {
        float a = g_qkv[n*QW + h] * SCALE;
        float D = horner13(cD, a);
        float num = 0.f;
        if (a > 0.f) {
            for (int i = 0; i < km; ++i) num = fmaf(__expf(0.f) * 0.f + expf(a * tk[i]), tv[i], num);
        } else if (a < 0.f) {
            for (int i = 0; i < km; ++i) num = fmaf(expf(a * bk[i]), bv[i], num);
        } else {
            for (int m = 0; m < km; ++m) num += g_qkv[m*QW + 128 + h];
        }
        g_lx[n*DIM + h] = num / D;
    }
}

// ---------------- kernel 5: fuse + residual + projection + early select ----------------
__global__ void k5_out(const float* __restrict__ x,
                       const float* __restrict__ fus_w, const float* __restrict__ fus_b,
                       const float* __restrict__ proj_w, const float* __restrict__ proj_b,
                       float* __restrict__ out) {
    int n = blockIdx.x, c = threadIdx.x;  // 64
    __shared__ float lx[DIM], gx[DIM], xm[DIM], t[DIM];
    __shared__ int early;
    lx[c] = g_lx[n*DIM + c];
    gx[c] = g_gx[n*DIM + c];
    xm[c] = g_xm[n*DIM + c];
    if (c == 0) early = g_early;
    __syncthreads();
    float f = fus_b[c];
#pragma unroll 8
    for (int j = 0; j < DIM; ++j) f = fmaf(lx[j], fus_w[j*DIM + c], f);
#pragma unroll 8
    for (int j = 0; j < DIM; ++j) f = fmaf(gx[j], fus_w[(DIM + j)*DIM + c], f);
    t[c] = xm[c] + f;
    __syncthreads();
    float o = proj_b[c];
#pragma unroll 8
    for (int j = 0; j < DIM; ++j) o = fmaf(t[j], proj_w[j*DIM + c], o);
    out[n*DIM + c] = early ? x[n*DIM + c] : o;
}

// ---------------- launch ----------------
extern "C" void kernel_launch(void* const* d_in, const int* in_sizes, int n_in,
                              void* d_out, int out_size) {
    const float* x      = (const float*)d_in[0];
    const float* qkv_w  = (const float*)d_in[1];
    const float* qkv_b  = (const float*)d_in[2];
    const float* gqkv_w = (const float*)d_in[3];
    const float* gqkv_b = (const float*)d_in[4];
    const float* cg_w   = (const float*)d_in[5];
    const float* cg_b   = (const float*)d_in[6];
    const float* hg_w   = (const float*)d_in[7];
    const float* hg_b   = (const float*)d_in[8];
    const float* fus_w  = (const float*)d_in[9];
    const float* fus_b  = (const float*)d_in[10];
    const float* proj_w = (const float*)d_in[11];
    const float* proj_b = (const float*)d_in[12];
    float* out = (float*)d_out;

    k0_importance<<<1, 64>>>(x, hg_w, hg_b);
    k1_gate_qkv<<<NN, QW>>>(x, cg_w, cg_b, qkv_w, qkv_b, gqkv_w, gqkv_b);
    k3_head<<<NH, 256>>>();
    k3b_km<<<1, 32>>>();
    k4_local<<<NH, 256>>>();
    k5_out<<<NN, DIM>>>(x, fus_w, fus_b, proj_w, proj_b, out);
}